// round 5
// baseline (speedup 1.0000x reference)
#include <cuda_runtime.h>
#include <cuda_fp16.h>
#include <cstddef>

// Problem constants
#define H 256
#define W 256
#define KW 129          // rfft bins along W
#define B_ 16
#define C_ 32
#define O_ 32
#define NIMG_X (B_*C_)  // 512
#define NIMG_W (O_*C_)  // 1024
#define NIMG_Y (B_*O_)  // 512

// ---------------- scratch (static device globals; allocation-free) ----------
__device__ __half2 g_xr[(size_t)KW * NIMG_X * H];
__device__ __half2 g_wr[(size_t)KW * NIMG_W * H];
__device__ __half2 g_xf[(size_t)H * KW * NIMG_X];
__device__ __half2 g_wf[(size_t)H * KW * NIMG_W];
__device__ __half2 g_yf[(size_t)H * KW * NIMG_Y];
__device__ __half2 g_yr[(size_t)KW * NIMG_Y * H];

__device__ __forceinline__ float2 cmulf(float2 a, float2 b) {
    return make_float2(fmaf(a.x, b.x, -a.y * b.y), fmaf(a.x, b.y, a.y * b.x));
}
__device__ __forceinline__ __half2 f2h(float2 v) { return __floats2half2_rn(v.x, v.y); }
__device__ __forceinline__ float2 h2f(__half2 v) { return __half22float2(v); }

// Packed f32x2 helpers (FFMA2 path — PTX-only per SASS_QUICKREF)
__device__ __forceinline__ unsigned long long pk2(float lo, float hi) {
    unsigned long long d;
    asm("mov.b64 %0, {%1, %2};" : "=l"(d) : "f"(lo), "f"(hi));
    return d;
}
__device__ __forceinline__ unsigned long long ffma2(unsigned long long a,
                                                    unsigned long long b,
                                                    unsigned long long c) {
    unsigned long long d;
    asm("fma.rn.f32x2 %0, %1, %2, %3;" : "=l"(d) : "l"(a), "l"(b), "l"(c));
    return d;
}
__device__ __forceinline__ float2 upk2(unsigned long long v) {
    float lo, hi;
    asm("mov.b64 {%0, %1}, %2;" : "=f"(lo), "=f"(hi) : "l"(v));
    return make_float2(lo, hi);
}

// ---------------- in-register FFT-16 (Stockham radix-2, 4 stages) -----------
template <bool INV>
__device__ __forceinline__ void fft16r(float2* a) {
    const float TR[8] = { 1.f,  0.9238795325112867f,  0.7071067811865476f,  0.3826834323650898f,
                          0.f, -0.3826834323650898f, -0.7071067811865476f, -0.9238795325112867f };
    const float TI[8] = { 0.f, -0.3826834323650898f, -0.7071067811865476f, -0.9238795325112867f,
                         -1.f, -0.9238795325112867f, -0.7071067811865476f, -0.3826834323650898f };
    float2 b[16];
    float2 *s = a, *d = b;
#pragma unroll
    for (int st = 0; st < 4; st++) {
        const int S = 1 << st;
#pragma unroll
        for (int t = 0; t < 8; t++) {
            const int j = t & ~(S - 1);
            const float wr = TR[j];
            const float wi = INV ? -TI[j] : TI[j];
            float2 u = s[t], v = s[t + 8];
            float2 sum = make_float2(u.x + v.x, u.y + v.y);
            float2 dif = make_float2(u.x - v.x, u.y - v.y);
            d[t + j]     = sum;
            d[t + j + S] = make_float2(fmaf(dif.x, wr, -dif.y * wi),
                                       fmaf(dif.x, wi,  dif.y * wr));
        }
        float2* tmp = s; s = d; d = tmp;
    }
}

// ---------------- FFT-256 on registers: 16 threads x 16 points --------------
template <bool INV>
__device__ __forceinline__ void fft256_regs(float2* a, float2* S,
                                            const float2* twd, int row, int t) {
    fft16r<INV>(a);
#pragma unroll
    for (int k2 = 0; k2 < 16; k2++) {
        float2 w = twd[t * k2];
        if (INV) w.y = -w.y;
        a[k2] = cmulf(a[k2], w);
    }
    float2* Sr = S + row * 272;
    __syncwarp();
#pragma unroll
    for (int k2 = 0; k2 < 16; k2++) Sr[t * 17 + k2] = a[k2];
    __syncwarp();
#pragma unroll
    for (int n1 = 0; n1 < 16; n1++) a[n1] = Sr[n1 * 17 + t];
    __syncwarp();
    fft16r<INV>(a);
}

// ---------------- K1: packed row FFT (2 real rows per complex FFT) ----------
__global__ void __launch_bounds__(256) k_rowfft(const float* __restrict__ in,
                                                __half2* __restrict__ out, int nimg) {
    __shared__ float2 S[4352];
    __shared__ float2 twd[256];
    const int tid = threadIdx.x, row = tid >> 4, t = tid & 15;
    const int img = blockIdx.x >> 3, h0 = (blockIdx.x & 7) << 5;
    { float sn, cs; sincosf(-6.283185307179586f * (float)tid / 256.0f, &sn, &cs);
      twd[tid] = make_float2(cs, sn); }
    const float* pa = in + ((size_t)img * H + h0 + 2 * row) * W + t;
    const float* pb = pa + W;
    float2 a[16];
#pragma unroll
    for (int q = 0; q < 16; q++) a[q] = make_float2(pa[q * 16], pb[q * 16]);
    __syncthreads();
    fft256_regs<false>(a, S, twd, row, t);
    __syncthreads();
#pragma unroll
    for (int k1 = 0; k1 < 16; k1++) S[(k1 * 16 + t) * 17 + row] = a[k1];
    __syncthreads();
    const size_t ob = (size_t)img * H + h0;
    for (int i = tid; i < KW * 32; i += 256) {
        const int kw_ = i >> 5, hh = i & 31, r = hh >> 1;
        const float2 Z  = S[kw_ * 17 + r];
        const float2 Zc = S[((256 - kw_) & 255) * 17 + r];
        float2 v;
        if ((hh & 1) == 0)
            v = make_float2((Z.x + Zc.x) * 0.5f, (Z.y - Zc.y) * 0.5f);
        else
            v = make_float2((Z.y + Zc.y) * 0.5f, (Zc.x - Z.x) * 0.5f);
        out[(size_t)kw_ * nimg * H + ob + hh] = f2h(v);
    }
}

// ---------------- K2: column FFT -> bin-major [kh][KW][nimg] (fp16) ---------
__global__ void __launch_bounds__(256) k_colfft(const __half2* __restrict__ in,
                                                __half2* __restrict__ out, int nimg) {
    __shared__ float2 S[4352];
    __shared__ float2 twd[256];
    const int tid = threadIdx.x, row = tid >> 4, t = tid & 15;
    const int kw = blockIdx.x, img0 = blockIdx.y << 4;
    { float sn, cs; sincosf(-6.283185307179586f * (float)tid / 256.0f, &sn, &cs);
      twd[tid] = make_float2(cs, sn); }
    const __half2* src = in + ((size_t)kw * nimg + img0 + row) * H + t;
    float2 a[16];
#pragma unroll
    for (int q = 0; q < 16; q++) a[q] = h2f(src[q * 16]);
    __syncthreads();
    fft256_regs<false>(a, S, twd, row, t);
    __syncthreads();
    __half2* Sh = (__half2*)S;          // alias: half-width staging
#pragma unroll
    for (int k1 = 0; k1 < 16; k1++) Sh[(k1 * 16 + t) * 17 + row] = f2h(a[k1]);
    __syncthreads();
    for (int i = tid; i < 4096; i += 256) {
        const int kh = i >> 4, im = i & 15;
        out[((size_t)kh * KW + kw) * nimg + img0 + im] = Sh[kh * 17 + im];
    }
}

// ---------------- K3: per-bin contraction, packed f32x2, 2 bins/block -------
// out[b,o] = sum_c x[b,c]*w[o,c] (complex). acc packs (re,im) in one b64.
__global__ void __launch_bounds__(256) k_bingemm(const __half2* __restrict__ xf,
                                                 const __half2* __restrict__ wf,
                                                 __half2* __restrict__ yf) {
    __shared__ __align__(16) unsigned long long sxa[2][512];  // [c*16+b] = (xr,xr)
    __shared__ __align__(16) unsigned long long sxb[2][512];  // [c*16+b] = (-xi,xi)
    __shared__ __align__(16) unsigned long long sw2[2][1024]; // [c*32+o] = (wr,wi)
    __shared__ __align__(16) unsigned long long sws[2][1024]; // [c*32+o] = (wi,wr)
    const int tid = threadIdx.x;
    const size_t bin0 = ((size_t)(blockIdx.y * 2)) * KW + blockIdx.x;  // kh=2y, kh=2y+1 at bin0+KW
    for (int i = tid; i < 1024; i += 256) {
        const int hf = i >> 9, j = i & 511;     // j = b*32+c
        const int b = j >> 5, c = j & 31;
        const float2 v = h2f(xf[(bin0 + (size_t)hf * KW) * NIMG_X + j]);
        sxa[hf][c * 16 + b] = pk2(v.x, v.x);
        sxb[hf][c * 16 + b] = pk2(-v.y, v.y);
    }
    for (int i = tid; i < 2048; i += 256) {
        const int hf = i >> 10, j = i & 1023;   // j = o*32+c
        const int o = j >> 5, c = j & 31;
        const float2 v = h2f(wf[(bin0 + (size_t)hf * KW) * NIMG_W + j]);
        sw2[hf][c * 32 + o] = pk2(v.x, v.y);
        sws[hf][c * 32 + o] = pk2(v.y, v.x);
    }
    __syncthreads();
    const int hb = tid >> 7, t7 = tid & 127, b2 = t7 >> 4, o2 = t7 & 15;
    unsigned long long a00 = 0, a01 = 0, a10 = 0, a11 = 0;
#pragma unroll
    for (int c = 0; c < 32; c++) {
        const ulonglong2 xa = *reinterpret_cast<const ulonglong2*>(&sxa[hb][c * 16 + 2 * b2]);
        const ulonglong2 xb = *reinterpret_cast<const ulonglong2*>(&sxb[hb][c * 16 + 2 * b2]);
        const ulonglong2 wv = *reinterpret_cast<const ulonglong2*>(&sw2[hb][c * 32 + 2 * o2]);
        const ulonglong2 ws = *reinterpret_cast<const ulonglong2*>(&sws[hb][c * 32 + 2 * o2]);
        a00 = ffma2(xa.x, wv.x, a00); a00 = ffma2(xb.x, ws.x, a00);
        a01 = ffma2(xa.x, wv.y, a01); a01 = ffma2(xb.x, ws.y, a01);
        a10 = ffma2(xa.y, wv.x, a10); a10 = ffma2(xb.y, ws.x, a10);
        a11 = ffma2(xa.y, wv.y, a11); a11 = ffma2(xb.y, ws.y, a11);
    }
    __half2* yb = yf + (bin0 + (size_t)hb * KW) * NIMG_Y;
    yb[(2 * b2 + 0) * 32 + 2 * o2 + 0] = f2h(upk2(a00));
    yb[(2 * b2 + 0) * 32 + 2 * o2 + 1] = f2h(upk2(a01));
    yb[(2 * b2 + 1) * 32 + 2 * o2 + 0] = f2h(upk2(a10));
    yb[(2 * b2 + 1) * 32 + 2 * o2 + 1] = f2h(upk2(a11));
}

// ---------------- K4: inverse column FFT -> [kw][nimg][h], scale 1/256 ------
__global__ void __launch_bounds__(256) k_icolfft(const __half2* __restrict__ in,
                                                 __half2* __restrict__ out, int nimg) {
    __shared__ float2 S[4352];
    __shared__ float2 twd[256];
    const int tid = threadIdx.x, row = tid >> 4, t = tid & 15;
    const int kw = blockIdx.x, img0 = blockIdx.y << 4;
    { float sn, cs; sincosf(-6.283185307179586f * (float)tid / 256.0f, &sn, &cs);
      twd[tid] = make_float2(cs, sn); }
    __half2* Sh = (__half2*)S;
    for (int i = tid; i < 4096; i += 256) {
        const int kh = i >> 4, im = i & 15;
        Sh[kh * 17 + im] = in[((size_t)kh * KW + kw) * nimg + img0 + im];
    }
    __syncthreads();
    float2 a[16];
#pragma unroll
    for (int q = 0; q < 16; q++) a[q] = h2f(Sh[(q * 16 + t) * 17 + row]);
    __syncthreads();
    fft256_regs<true>(a, S, twd, row, t);
    __syncthreads();
    const float sc = 1.0f / 256.0f;
#pragma unroll
    for (int k1 = 0; k1 < 16; k1++)
        Sh[row * 272 + k1 * 16 + t] = f2h(make_float2(a[k1].x * sc, a[k1].y * sc));
    __syncthreads();
    for (int i = tid; i < 4096; i += 256) {
        const int im = i >> 8, h = i & 255;
        out[((size_t)kw * nimg + img0 + im) * H + h] = Sh[im * 272 + h];
    }
}

// ---------------- K5: packed inverse row FFT (2 real rows per iFFT) ---------
__global__ void __launch_bounds__(256) k_irowfft(const __half2* __restrict__ in,
                                                 float* __restrict__ out, int nimg) {
    __shared__ float2 S[4352];
    __shared__ float2 twd[256];
    const int tid = threadIdx.x, row = tid >> 4, t = tid & 15;
    const int img = blockIdx.x >> 3, h0 = (blockIdx.x & 7) << 5;
    { float sn, cs; sincosf(-6.283185307179586f * (float)tid / 256.0f, &sn, &cs);
      twd[tid] = make_float2(cs, sn); }
    __half2* Sh = (__half2*)S;
    for (int i = tid; i < KW * 32; i += 256) {
        const int kw_ = i >> 5, hh = i & 31;
        Sh[kw_ * 33 + hh] = in[(size_t)kw_ * nimg * H + (size_t)img * H + h0 + hh];
    }
    __syncthreads();
    float2 a[16];
#pragma unroll
    for (int q = 0; q < 16; q++) {
        const int n = q * 16 + t;
        if (n <= 128) {
            const float2 ya = h2f(Sh[n * 33 + 2 * row]);
            const float2 yb = h2f(Sh[n * 33 + 2 * row + 1]);
            a[q] = make_float2(ya.x - yb.y, ya.y + yb.x);        // Ya + i*Yb
        } else {
            const int m = 256 - n;
            const float2 ya = h2f(Sh[m * 33 + 2 * row]);
            const float2 yb = h2f(Sh[m * 33 + 2 * row + 1]);
            a[q] = make_float2(ya.x + yb.y, yb.x - ya.y);        // conj(Ya)+i*conj(Yb)
        }
    }
    __syncthreads();
    fft256_regs<true>(a, S, twd, row, t);
    __syncthreads();
    float* Sf = (float*)S;
    const float sc = 1.0f / 256.0f;
#pragma unroll
    for (int k1 = 0; k1 < 16; k1++) {
        const int idx = k1 * 16 + t;
        Sf[(2 * row) * 256 + idx]     = a[k1].x * sc;
        Sf[(2 * row + 1) * 256 + idx] = a[k1].y * sc;
    }
    __syncthreads();
    const size_t ob = ((size_t)img * H + h0) * W;
    for (int i = tid; i < 8192; i += 256)
        out[ob + (size_t)(i >> 8) * W + (i & 255)] = Sf[i];
}

// ---------------------------------------------------------------------------
extern "C" void kernel_launch(void* const* d_in, const int* in_sizes, int n_in,
                              void* d_out, int out_size) {
    (void)in_sizes; (void)n_in; (void)out_size;
    const float* x = (const float*)d_in[0];   // (B,C,H,W)
    const float* w = (const float*)d_in[1];   // (O,C,H,W)
    float* out = (float*)d_out;               // (B,O,H,W)

    __half2 *xr, *wr, *xf, *wf, *yf, *yr;
    cudaGetSymbolAddress((void**)&xr, g_xr);
    cudaGetSymbolAddress((void**)&wr, g_wr);
    cudaGetSymbolAddress((void**)&xf, g_xf);
    cudaGetSymbolAddress((void**)&wf, g_wf);
    cudaGetSymbolAddress((void**)&yf, g_yf);
    cudaGetSymbolAddress((void**)&yr, g_yr);

    // Packed forward row FFTs (2 real rows per complex FFT)
    k_rowfft<<<NIMG_X * 8, 256>>>(x, xr, NIMG_X);
    k_rowfft<<<NIMG_W * 8, 256>>>(w, wr, NIMG_W);
    // Forward column FFTs -> bin-major
    k_colfft<<<dim3(KW, NIMG_X / 16), 256>>>(xr, xf, NIMG_X);
    k_colfft<<<dim3(KW, NIMG_W / 16), 256>>>(wr, wf, NIMG_W);
    // Per-bin channel contraction (packed f32x2 FMA, 2 kh-bins per block)
    k_bingemm<<<dim3(KW, H / 2), 256>>>(xf, wf, yf);
    // Inverse column FFT (fp16 in/out)
    k_icolfft<<<dim3(KW, NIMG_Y / 16), 256>>>(yf, yr, NIMG_Y);
    // Packed inverse row FFT -> real output
    k_irowfft<<<NIMG_Y * 8, 256>>>(yr, out, NIMG_Y);
}

// round 6
// speedup vs baseline: 2.7361x; 2.7361x over previous
#include <cuda_runtime.h>
#include <cuda_fp16.h>
#include <cstddef>

// Problem constants
#define H 256
#define W 256
#define KW 129          // rfft bins along W
#define B_ 16
#define C_ 32
#define O_ 32
#define NIMG_X (B_*C_)  // 512
#define NIMG_W (O_*C_)  // 1024
#define NIMG_Y (B_*O_)  // 512

// ---------------- scratch (static device globals; allocation-free) ----------
__device__ __half2 g_xr[(size_t)KW * NIMG_X * H];
__device__ __half2 g_wr[(size_t)KW * NIMG_W * H];
__device__ __half2 g_xf[(size_t)H * KW * NIMG_X];
__device__ __half2 g_wf[(size_t)H * KW * NIMG_W];
__device__ __half2 g_yf[(size_t)H * KW * NIMG_Y];
__device__ __half2 g_yr[(size_t)KW * NIMG_Y * H];

__device__ __forceinline__ float2 cmulf(float2 a, float2 b) {
    return make_float2(fmaf(a.x, b.x, -a.y * b.y), fmaf(a.x, b.y, a.y * b.x));
}
__device__ __forceinline__ __half2 f2h(float2 v) { return __floats2half2_rn(v.x, v.y); }
__device__ __forceinline__ float2 h2f(__half2 v) { return __half22float2(v); }

// ---------------- in-register FFT-16 (Stockham radix-2, 4 stages) -----------
template <bool INV>
__device__ __forceinline__ void fft16r(float2* a) {
    const float TR[8] = { 1.f,  0.9238795325112867f,  0.7071067811865476f,  0.3826834323650898f,
                          0.f, -0.3826834323650898f, -0.7071067811865476f, -0.9238795325112867f };
    const float TI[8] = { 0.f, -0.3826834323650898f, -0.7071067811865476f, -0.9238795325112867f,
                         -1.f, -0.9238795325112867f, -0.7071067811865476f, -0.3826834323650898f };
    float2 b[16];
    float2 *s = a, *d = b;
#pragma unroll
    for (int st = 0; st < 4; st++) {
        const int S = 1 << st;
#pragma unroll
        for (int t = 0; t < 8; t++) {
            const int j = t & ~(S - 1);
            const float wr = TR[j];
            const float wi = INV ? -TI[j] : TI[j];
            float2 u = s[t], v = s[t + 8];
            float2 sum = make_float2(u.x + v.x, u.y + v.y);
            float2 dif = make_float2(u.x - v.x, u.y - v.y);
            d[t + j]     = sum;
            d[t + j + S] = make_float2(fmaf(dif.x, wr, -dif.y * wi),
                                       fmaf(dif.x, wi,  dif.y * wr));
        }
        float2* tmp = s; s = d; d = tmp;
    }
}

// ---------------- FFT-256 on registers: 16 threads x 16 points --------------
template <bool INV>
__device__ __forceinline__ void fft256_regs(float2* a, float2* S,
                                            const float2* twd, int row, int t) {
    fft16r<INV>(a);
#pragma unroll
    for (int k2 = 0; k2 < 16; k2++) {
        float2 w = twd[t * k2];
        if (INV) w.y = -w.y;
        a[k2] = cmulf(a[k2], w);
    }
    float2* Sr = S + row * 272;
    __syncwarp();
#pragma unroll
    for (int k2 = 0; k2 < 16; k2++) Sr[t * 17 + k2] = a[k2];
    __syncwarp();
#pragma unroll
    for (int n1 = 0; n1 < 16; n1++) a[n1] = Sr[n1 * 17 + t];
    __syncwarp();
    fft16r<INV>(a);
}

// ---------------- K1: packed row FFT (2 real rows per complex FFT) ----------
__global__ void __launch_bounds__(256) k_rowfft(const float* __restrict__ in,
                                                __half2* __restrict__ out, int nimg) {
    __shared__ float2 S[4352];
    __shared__ float2 twd[256];
    const int tid = threadIdx.x, row = tid >> 4, t = tid & 15;
    const int img = blockIdx.x >> 3, h0 = (blockIdx.x & 7) << 5;
    { float sn, cs; sincosf(-6.283185307179586f * (float)tid / 256.0f, &sn, &cs);
      twd[tid] = make_float2(cs, sn); }
    const float* pa = in + ((size_t)img * H + h0 + 2 * row) * W + t;
    const float* pb = pa + W;
    float2 a[16];
#pragma unroll
    for (int q = 0; q < 16; q++) a[q] = make_float2(pa[q * 16], pb[q * 16]);
    __syncthreads();
    fft256_regs<false>(a, S, twd, row, t);
    __syncthreads();
#pragma unroll
    for (int k1 = 0; k1 < 16; k1++) S[(k1 * 16 + t) * 17 + row] = a[k1];
    __syncthreads();
    const size_t ob = (size_t)img * H + h0;
    for (int i = tid; i < KW * 32; i += 256) {
        const int kw_ = i >> 5, hh = i & 31, r = hh >> 1;
        const float2 Z  = S[kw_ * 17 + r];
        const float2 Zc = S[((256 - kw_) & 255) * 17 + r];
        float2 v;
        if ((hh & 1) == 0)
            v = make_float2((Z.x + Zc.x) * 0.5f, (Z.y - Zc.y) * 0.5f);
        else
            v = make_float2((Z.y + Zc.y) * 0.5f, (Zc.x - Z.x) * 0.5f);
        out[(size_t)kw_ * nimg * H + ob + hh] = f2h(v);
    }
}

// ---------------- K2: column FFT -> bin-major [kh][KW][nimg] (fp16) ---------
__global__ void __launch_bounds__(256) k_colfft(const __half2* __restrict__ in,
                                                __half2* __restrict__ out, int nimg) {
    __shared__ float2 S[4352];
    __shared__ float2 twd[256];
    const int tid = threadIdx.x, row = tid >> 4, t = tid & 15;
    const int kw = blockIdx.x, img0 = blockIdx.y << 4;
    { float sn, cs; sincosf(-6.283185307179586f * (float)tid / 256.0f, &sn, &cs);
      twd[tid] = make_float2(cs, sn); }
    const __half2* src = in + ((size_t)kw * nimg + img0 + row) * H + t;
    float2 a[16];
#pragma unroll
    for (int q = 0; q < 16; q++) a[q] = h2f(src[q * 16]);
    __syncthreads();
    fft256_regs<false>(a, S, twd, row, t);
    __syncthreads();
#pragma unroll
    for (int k1 = 0; k1 < 16; k1++) S[(k1 * 16 + t) * 17 + row] = a[k1];
    __syncthreads();
    for (int i = tid; i < 4096; i += 256) {
        const int kh = i >> 4, im = i & 15;
        out[((size_t)kh * KW + kw) * nimg + img0 + im] = f2h(S[kh * 17 + im]);
    }
}

// ---------------- K3: per-bin contraction on tensor cores (mma.sync) --------
// Per bin: complex GEMM out[b,o] = sum_c x[b,c]*w[o,c] as 2 real GEMMs, K=64.
// A[16x64] = xf bin block as half[64] rows ([xr xi] interleaved).
// B_re col o = (wr,-wi) pairs (hi-half sign flip); B_im = (wi,wr) (halves swapped).
// 1 warp = 1 bin, 4 bins/block. fp32 accumulate.
__device__ __forceinline__ void mma16816(float* c, const unsigned* a, unsigned b0, unsigned b1) {
    asm volatile("mma.sync.aligned.m16n8k16.row.col.f32.f16.f16.f32 "
                 "{%0,%1,%2,%3}, {%4,%5,%6,%7}, {%8,%9}, {%0,%1,%2,%3};"
                 : "+f"(c[0]), "+f"(c[1]), "+f"(c[2]), "+f"(c[3])
                 : "r"(a[0]), "r"(a[1]), "r"(a[2]), "r"(a[3]), "r"(b0), "r"(b1));
}

__global__ void __launch_bounds__(128) k_bingemm(const __half2* __restrict__ xf,
                                                 const __half2* __restrict__ wf,
                                                 __half2* __restrict__ yf) {
    __shared__ unsigned xs[4][16 * 36];   // [bin][b*36 + cpair], padded stride 36
    __shared__ unsigned ws[4][32 * 36];   // [bin][o*36 + cpair]
    const int tid = threadIdx.x;
    const size_t gbin0 = (size_t)blockIdx.x * 4;
    const unsigned* xg = (const unsigned*)(xf + gbin0 * NIMG_X);
    const unsigned* wg = (const unsigned*)(wf + gbin0 * NIMG_W);
    for (int i = tid; i < 4 * 512; i += 128) {
        const int lb = i >> 9, j = i & 511;
        xs[lb][(j >> 5) * 36 + (j & 31)] = xg[lb * 512 + j];
    }
    for (int i = tid; i < 4 * 1024; i += 128) {
        const int lb = i >> 10, j = i & 1023;
        ws[lb][(j >> 5) * 36 + (j & 31)] = wg[lb * 1024 + j];
    }
    __syncthreads();
    const int wp = tid >> 5, lane = tid & 31, r = lane >> 2, q = lane & 3;
    const unsigned* X = xs[wp];
    const unsigned* Wm = ws[wp];
    float cre[4][4] = {{0}}, cim[4][4] = {{0}};
#pragma unroll
    for (int kc = 0; kc < 4; kc++) {
        unsigned a[4];
        a[0] = X[r * 36 + kc * 8 + q];
        a[1] = X[(r + 8) * 36 + kc * 8 + q];
        a[2] = X[r * 36 + kc * 8 + 4 + q];
        a[3] = X[(r + 8) * 36 + kc * 8 + 4 + q];
#pragma unroll
        for (int ot = 0; ot < 4; ot++) {
            const unsigned w0 = Wm[(ot * 8 + r) * 36 + kc * 8 + q];
            const unsigned w1 = Wm[(ot * 8 + r) * 36 + kc * 8 + 4 + q];
            mma16816(cre[ot], a, w0 ^ 0x80000000u, w1 ^ 0x80000000u);   // (wr,-wi)
            mma16816(cim[ot], a, __byte_perm(w0, w0, 0x1032),           // (wi,wr)
                                  __byte_perm(w1, w1, 0x1032));
        }
    }
    __half2* Y = yf + (gbin0 + wp) * NIMG_Y;
#pragma unroll
    for (int ot = 0; ot < 4; ot++) {
        const int o0 = ot * 8 + 2 * q;
        Y[r * 32 + o0]           = f2h(make_float2(cre[ot][0], cim[ot][0]));
        Y[r * 32 + o0 + 1]       = f2h(make_float2(cre[ot][1], cim[ot][1]));
        Y[(r + 8) * 32 + o0]     = f2h(make_float2(cre[ot][2], cim[ot][2]));
        Y[(r + 8) * 32 + o0 + 1] = f2h(make_float2(cre[ot][3], cim[ot][3]));
    }
}

// ---------------- K4: inverse column FFT -> [kw][nimg][h], scale 1/256 ------
__global__ void __launch_bounds__(256) k_icolfft(const __half2* __restrict__ in,
                                                 __half2* __restrict__ out, int nimg) {
    __shared__ float2 S[4352];
    __shared__ float2 twd[256];
    const int tid = threadIdx.x, row = tid >> 4, t = tid & 15;
    const int kw = blockIdx.x, img0 = blockIdx.y << 4;
    { float sn, cs; sincosf(-6.283185307179586f * (float)tid / 256.0f, &sn, &cs);
      twd[tid] = make_float2(cs, sn); }
    for (int i = tid; i < 4096; i += 256) {
        const int kh = i >> 4, im = i & 15;
        S[kh * 17 + im] = h2f(in[((size_t)kh * KW + kw) * nimg + img0 + im]);
    }
    __syncthreads();
    float2 a[16];
#pragma unroll
    for (int q = 0; q < 16; q++) a[q] = S[(q * 16 + t) * 17 + row];
    __syncthreads();
    fft256_regs<true>(a, S, twd, row, t);
    __syncthreads();
    const float sc = 1.0f / 256.0f;
#pragma unroll
    for (int k1 = 0; k1 < 16; k1++)
        S[row * 256 + k1 * 16 + t] = make_float2(a[k1].x * sc, a[k1].y * sc);
    __syncthreads();
    for (int i = tid; i < 4096; i += 256) {
        const int im = i >> 8, h = i & 255;
        out[((size_t)kw * nimg + img0 + im) * H + h] = f2h(S[im * 256 + h]);
    }
}

// ---------------- K5: packed inverse row FFT (2 real rows per iFFT) ---------
__global__ void __launch_bounds__(256) k_irowfft(const __half2* __restrict__ in,
                                                 float* __restrict__ out, int nimg) {
    __shared__ float2 S[4352];
    __shared__ float2 twd[256];
    const int tid = threadIdx.x, row = tid >> 4, t = tid & 15;
    const int img = blockIdx.x >> 3, h0 = (blockIdx.x & 7) << 5;
    { float sn, cs; sincosf(-6.283185307179586f * (float)tid / 256.0f, &sn, &cs);
      twd[tid] = make_float2(cs, sn); }
    for (int i = tid; i < KW * 32; i += 256) {
        const int kw_ = i >> 5, hh = i & 31;
        S[kw_ * 33 + hh] = h2f(in[(size_t)kw_ * nimg * H + (size_t)img * H + h0 + hh]);
    }
    __syncthreads();
    float2 a[16];
#pragma unroll
    for (int q = 0; q < 16; q++) {
        const int n = q * 16 + t;
        if (n <= 128) {
            const float2 ya = S[n * 33 + 2 * row];
            const float2 yb = S[n * 33 + 2 * row + 1];
            a[q] = make_float2(ya.x - yb.y, ya.y + yb.x);        // Ya + i*Yb
        } else {
            const int m = 256 - n;
            const float2 ya = S[m * 33 + 2 * row];
            const float2 yb = S[m * 33 + 2 * row + 1];
            a[q] = make_float2(ya.x + yb.y, yb.x - ya.y);        // conj(Ya)+i*conj(Yb)
        }
    }
    __syncthreads();
    fft256_regs<true>(a, S, twd, row, t);
    __syncthreads();
    float* Sf = (float*)S;
    const float sc = 1.0f / 256.0f;
#pragma unroll
    for (int k1 = 0; k1 < 16; k1++) {
        const int idx = k1 * 16 + t;
        Sf[(2 * row) * 256 + idx]     = a[k1].x * sc;
        Sf[(2 * row + 1) * 256 + idx] = a[k1].y * sc;
    }
    __syncthreads();
    const size_t ob = ((size_t)img * H + h0) * W;
    for (int i = tid; i < 8192; i += 256)
        out[ob + (size_t)(i >> 8) * W + (i & 255)] = Sf[i];
}

// ---------------------------------------------------------------------------
extern "C" void kernel_launch(void* const* d_in, const int* in_sizes, int n_in,
                              void* d_out, int out_size) {
    (void)in_sizes; (void)n_in; (void)out_size;
    const float* x = (const float*)d_in[0];   // (B,C,H,W)
    const float* w = (const float*)d_in[1];   // (O,C,H,W)
    float* out = (float*)d_out;               // (B,O,H,W)

    __half2 *xr, *wr, *xf, *wf, *yf, *yr;
    cudaGetSymbolAddress((void**)&xr, g_xr);
    cudaGetSymbolAddress((void**)&wr, g_wr);
    cudaGetSymbolAddress((void**)&xf, g_xf);
    cudaGetSymbolAddress((void**)&wf, g_wf);
    cudaGetSymbolAddress((void**)&yf, g_yf);
    cudaGetSymbolAddress((void**)&yr, g_yr);

    // Packed forward row FFTs (2 real rows per complex FFT)
    k_rowfft<<<NIMG_X * 8, 256>>>(x, xr, NIMG_X);
    k_rowfft<<<NIMG_W * 8, 256>>>(w, wr, NIMG_W);
    // Forward column FFTs -> bin-major
    k_colfft<<<dim3(KW, NIMG_X / 16), 256>>>(xr, xf, NIMG_X);
    k_colfft<<<dim3(KW, NIMG_W / 16), 256>>>(wr, wf, NIMG_W);
    // Per-bin channel contraction on tensor cores (4 bins/block, 1 warp/bin)
    k_bingemm<<<(H * KW) / 4, 128>>>(xf, wf, yf);
    // Inverse column FFT (fp16 in/out)
    k_icolfft<<<dim3(KW, NIMG_Y / 16), 256>>>(yf, yr, NIMG_Y);
    // Packed inverse row FFT -> real output
    k_irowfft<<<NIMG_Y * 8, 256>>>(yr, out, NIMG_Y);
}

// round 7
// speedup vs baseline: 3.0110x; 1.1005x over previous
#include <cuda_runtime.h>
#include <cuda_fp16.h>
#include <cstddef>

// Problem constants
#define H 256
#define W 256
#define KW 129          // rfft bins along W
#define B_ 16
#define C_ 32
#define O_ 32
#define NIMG_X (B_*C_)  // 512
#define NIMG_W (O_*C_)  // 1024
#define NIMG_Y (B_*O_)  // 512

// ---------------- scratch (static device globals; allocation-free) ----------
__device__ __half2 g_xr[(size_t)KW * NIMG_X * H];
__device__ __half2 g_wr[(size_t)KW * NIMG_W * H];
__device__ __half2 g_xf[(size_t)H * KW * NIMG_X];
__device__ __half2 g_wf[(size_t)H * KW * NIMG_W];
__device__ __half2 g_yf[(size_t)H * KW * NIMG_Y];
__device__ __half2 g_yr[(size_t)KW * NIMG_Y * H];

__device__ __forceinline__ float2 cmulf(float2 a, float2 b) {
    return make_float2(fmaf(a.x, b.x, -a.y * b.y), fmaf(a.x, b.y, a.y * b.x));
}
__device__ __forceinline__ __half2 f2h(float2 v) { return __floats2half2_rn(v.x, v.y); }
__device__ __forceinline__ float2 h2f(__half2 v) { return __half22float2(v); }
// streaming (last-use) half2 load
__device__ __forceinline__ __half2 ldcs_h2(const __half2* p) {
    unsigned u = __ldcs((const unsigned*)p);
    return *reinterpret_cast<__half2*>(&u);
}

// ---------------- in-register FFT-16 (Stockham radix-2, 4 stages) -----------
template <bool INV>
__device__ __forceinline__ void fft16r(float2* a) {
    const float TR[8] = { 1.f,  0.9238795325112867f,  0.7071067811865476f,  0.3826834323650898f,
                          0.f, -0.3826834323650898f, -0.7071067811865476f, -0.9238795325112867f };
    const float TI[8] = { 0.f, -0.3826834323650898f, -0.7071067811865476f, -0.9238795325112867f,
                         -1.f, -0.9238795325112867f, -0.7071067811865476f, -0.3826834323650898f };
    float2 b[16];
    float2 *s = a, *d = b;
#pragma unroll
    for (int st = 0; st < 4; st++) {
        const int S = 1 << st;
#pragma unroll
        for (int t = 0; t < 8; t++) {
            const int j = t & ~(S - 1);
            const float wr = TR[j];
            const float wi = INV ? -TI[j] : TI[j];
            float2 u = s[t], v = s[t + 8];
            float2 sum = make_float2(u.x + v.x, u.y + v.y);
            float2 dif = make_float2(u.x - v.x, u.y - v.y);
            d[t + j]     = sum;
            d[t + j + S] = make_float2(fmaf(dif.x, wr, -dif.y * wi),
                                       fmaf(dif.x, wi,  dif.y * wr));
        }
        float2* tmp = s; s = d; d = tmp;
    }
}

// ---------------- FFT-256 on registers: 16 threads x 16 points --------------
template <bool INV>
__device__ __forceinline__ void fft256_regs(float2* a, float2* S,
                                            const float2* twd, int row, int t) {
    fft16r<INV>(a);
#pragma unroll
    for (int k2 = 0; k2 < 16; k2++) {
        float2 w = twd[t * k2];
        if (INV) w.y = -w.y;
        a[k2] = cmulf(a[k2], w);
    }
    float2* Sr = S + row * 272;
    __syncwarp();
#pragma unroll
    for (int k2 = 0; k2 < 16; k2++) Sr[t * 17 + k2] = a[k2];
    __syncwarp();
#pragma unroll
    for (int n1 = 0; n1 < 16; n1++) a[n1] = Sr[n1 * 17 + t];
    __syncwarp();
    fft16r<INV>(a);
}

// ---------------- K1: packed row FFT (2 real rows per complex FFT) ----------
__global__ void __launch_bounds__(256) k_rowfft(const float* __restrict__ in,
                                                __half2* __restrict__ out, int nimg) {
    __shared__ float2 S[4352];
    __shared__ float2 twd[256];
    const int tid = threadIdx.x, row = tid >> 4, t = tid & 15;
    const int img = blockIdx.x >> 3, h0 = (blockIdx.x & 7) << 5;
    { float sn, cs; sincosf(-6.283185307179586f * (float)tid / 256.0f, &sn, &cs);
      twd[tid] = make_float2(cs, sn); }
    const float* pa = in + ((size_t)img * H + h0 + 2 * row) * W + t;
    const float* pb = pa + W;
    float2 a[16];
#pragma unroll
    for (int q = 0; q < 16; q++) a[q] = make_float2(__ldcs(pa + q * 16), __ldcs(pb + q * 16));
    __syncthreads();
    fft256_regs<false>(a, S, twd, row, t);
    __syncthreads();
#pragma unroll
    for (int k1 = 0; k1 < 16; k1++) S[(k1 * 16 + t) * 17 + row] = a[k1];
    __syncthreads();
    const size_t ob = (size_t)img * H + h0;
    for (int i = tid; i < KW * 32; i += 256) {
        const int kw_ = i >> 5, hh = i & 31, r = hh >> 1;
        const float2 Z  = S[kw_ * 17 + r];
        const float2 Zc = S[((256 - kw_) & 255) * 17 + r];
        float2 v;
        if ((hh & 1) == 0)
            v = make_float2((Z.x + Zc.x) * 0.5f, (Z.y - Zc.y) * 0.5f);
        else
            v = make_float2((Z.y + Zc.y) * 0.5f, (Zc.x - Z.x) * 0.5f);
        out[(size_t)kw_ * nimg * H + ob + hh] = f2h(v);
    }
}

// ---------------- K2: column FFT -> bin-major [kh][KW][nimg] (fp16) ---------
__global__ void __launch_bounds__(256) k_colfft(const __half2* __restrict__ in,
                                                __half2* __restrict__ out, int nimg) {
    __shared__ float2 S[4352];
    __shared__ float2 twd[256];
    const int tid = threadIdx.x, row = tid >> 4, t = tid & 15;
    const int kw = blockIdx.x, img0 = blockIdx.y << 4;
    { float sn, cs; sincosf(-6.283185307179586f * (float)tid / 256.0f, &sn, &cs);
      twd[tid] = make_float2(cs, sn); }
    const __half2* src = in + ((size_t)kw * nimg + img0 + row) * H + t;
    float2 a[16];
#pragma unroll
    for (int q = 0; q < 16; q++) a[q] = h2f(ldcs_h2(src + q * 16));
    __syncthreads();
    fft256_regs<false>(a, S, twd, row, t);
    __syncthreads();
#pragma unroll
    for (int k1 = 0; k1 < 16; k1++) S[(k1 * 16 + t) * 17 + row] = a[k1];
    __syncthreads();
    for (int i = tid; i < 4096; i += 256) {
        const int kh = i >> 4, im = i & 15;
        out[((size_t)kh * KW + kw) * nimg + img0 + im] = f2h(S[kh * 17 + im]);
    }
}

// ---------------- K3: per-bin contraction on tensor cores (mma.sync) --------
__device__ __forceinline__ void mma16816(float* c, const unsigned* a, unsigned b0, unsigned b1) {
    asm volatile("mma.sync.aligned.m16n8k16.row.col.f32.f16.f16.f32 "
                 "{%0,%1,%2,%3}, {%4,%5,%6,%7}, {%8,%9}, {%0,%1,%2,%3};"
                 : "+f"(c[0]), "+f"(c[1]), "+f"(c[2]), "+f"(c[3])
                 : "r"(a[0]), "r"(a[1]), "r"(a[2]), "r"(a[3]), "r"(b0), "r"(b1));
}

__global__ void __launch_bounds__(128) k_bingemm(const __half2* __restrict__ xf,
                                                 const __half2* __restrict__ wf,
                                                 __half2* __restrict__ yf) {
    __shared__ unsigned xs[4][16 * 36];   // [bin][b*36 + cpair], padded stride 36
    __shared__ unsigned ws[4][32 * 36];   // [bin][o*36 + cpair]
    const int tid = threadIdx.x;
    const size_t gbin0 = (size_t)blockIdx.x * 4;
    const unsigned* xg = (const unsigned*)(xf + gbin0 * NIMG_X);
    const unsigned* wg = (const unsigned*)(wf + gbin0 * NIMG_W);
    for (int i = tid; i < 4 * 512; i += 128) {
        const int lb = i >> 9, j = i & 511;
        xs[lb][(j >> 5) * 36 + (j & 31)] = __ldcs(xg + lb * 512 + j);
    }
    for (int i = tid; i < 4 * 1024; i += 128) {
        const int lb = i >> 10, j = i & 1023;
        ws[lb][(j >> 5) * 36 + (j & 31)] = __ldcs(wg + lb * 1024 + j);
    }
    __syncthreads();
    const int wp = tid >> 5, lane = tid & 31, r = lane >> 2, q = lane & 3;
    const unsigned* X = xs[wp];
    const unsigned* Wm = ws[wp];
    float cre[4][4] = {{0}}, cim[4][4] = {{0}};
#pragma unroll
    for (int kc = 0; kc < 4; kc++) {
        unsigned a[4];
        a[0] = X[r * 36 + kc * 8 + q];
        a[1] = X[(r + 8) * 36 + kc * 8 + q];
        a[2] = X[r * 36 + kc * 8 + 4 + q];
        a[3] = X[(r + 8) * 36 + kc * 8 + 4 + q];
#pragma unroll
        for (int ot = 0; ot < 4; ot++) {
            const unsigned w0 = Wm[(ot * 8 + r) * 36 + kc * 8 + q];
            const unsigned w1 = Wm[(ot * 8 + r) * 36 + kc * 8 + 4 + q];
            mma16816(cre[ot], a, w0 ^ 0x80000000u, w1 ^ 0x80000000u);   // (wr,-wi)
            mma16816(cim[ot], a, __byte_perm(w0, w0, 0x1032),           // (wi,wr)
                                  __byte_perm(w1, w1, 0x1032));
        }
    }
    __half2* Y = yf + (gbin0 + wp) * NIMG_Y;
#pragma unroll
    for (int ot = 0; ot < 4; ot++) {
        const int o0 = ot * 8 + 2 * q;
        Y[r * 32 + o0]           = f2h(make_float2(cre[ot][0], cim[ot][0]));
        Y[r * 32 + o0 + 1]       = f2h(make_float2(cre[ot][1], cim[ot][1]));
        Y[(r + 8) * 32 + o0]     = f2h(make_float2(cre[ot][2], cim[ot][2]));
        Y[(r + 8) * 32 + o0 + 1] = f2h(make_float2(cre[ot][3], cim[ot][3]));
    }
}

// ---------------- K4: inverse column FFT -> [kw][nimg][h], scale 1/256 ------
__global__ void __launch_bounds__(256) k_icolfft(const __half2* __restrict__ in,
                                                 __half2* __restrict__ out, int nimg) {
    __shared__ float2 S[4352];
    __shared__ float2 twd[256];
    const int tid = threadIdx.x, row = tid >> 4, t = tid & 15;
    const int kw = blockIdx.x, img0 = blockIdx.y << 4;
    { float sn, cs; sincosf(-6.283185307179586f * (float)tid / 256.0f, &sn, &cs);
      twd[tid] = make_float2(cs, sn); }
    for (int i = tid; i < 4096; i += 256) {
        const int kh = i >> 4, im = i & 15;
        S[kh * 17 + im] = h2f(ldcs_h2(in + ((size_t)kh * KW + kw) * nimg + img0 + im));
    }
    __syncthreads();
    float2 a[16];
#pragma unroll
    for (int q = 0; q < 16; q++) a[q] = S[(q * 16 + t) * 17 + row];
    __syncthreads();
    fft256_regs<true>(a, S, twd, row, t);
    __syncthreads();
    const float sc = 1.0f / 256.0f;
#pragma unroll
    for (int k1 = 0; k1 < 16; k1++)
        S[row * 256 + k1 * 16 + t] = make_float2(a[k1].x * sc, a[k1].y * sc);
    __syncthreads();
    for (int i = tid; i < 4096; i += 256) {
        const int im = i >> 8, h = i & 255;
        out[((size_t)kw * nimg + img0 + im) * H + h] = f2h(S[im * 256 + h]);
    }
}

// ---------------- K5: packed inverse row FFT (2 real rows per iFFT) ---------
__global__ void __launch_bounds__(256) k_irowfft(const __half2* __restrict__ in,
                                                 float* __restrict__ out, int nimg) {
    __shared__ float2 S[4352];
    __shared__ float2 twd[256];
    const int tid = threadIdx.x, row = tid >> 4, t = tid & 15;
    const int img = blockIdx.x >> 3, h0 = (blockIdx.x & 7) << 5;
    { float sn, cs; sincosf(-6.283185307179586f * (float)tid / 256.0f, &sn, &cs);
      twd[tid] = make_float2(cs, sn); }
    for (int i = tid; i < KW * 32; i += 256) {
        const int kw_ = i >> 5, hh = i & 31;
        S[kw_ * 33 + hh] = h2f(ldcs_h2(in + (size_t)kw_ * nimg * H + (size_t)img * H + h0 + hh));
    }
    __syncthreads();
    float2 a[16];
#pragma unroll
    for (int q = 0; q < 16; q++) {
        const int n = q * 16 + t;
        if (n <= 128) {
            const float2 ya = S[n * 33 + 2 * row];
            const float2 yb = S[n * 33 + 2 * row + 1];
            a[q] = make_float2(ya.x - yb.y, ya.y + yb.x);        // Ya + i*Yb
        } else {
            const int m = 256 - n;
            const float2 ya = S[m * 33 + 2 * row];
            const float2 yb = S[m * 33 + 2 * row + 1];
            a[q] = make_float2(ya.x + yb.y, yb.x - ya.y);        // conj(Ya)+i*conj(Yb)
        }
    }
    __syncthreads();
    fft256_regs<true>(a, S, twd, row, t);
    __syncthreads();
    float* Sf = (float*)S;
    const float sc = 1.0f / 256.0f;
#pragma unroll
    for (int k1 = 0; k1 < 16; k1++) {
        const int idx = k1 * 16 + t;
        Sf[(2 * row) * 256 + idx]     = a[k1].x * sc;
        Sf[(2 * row + 1) * 256 + idx] = a[k1].y * sc;
    }
    __syncthreads();
    const size_t ob = ((size_t)img * H + h0) * W;
    for (int i = tid; i < 8192; i += 256)
        __stcs(out + ob + (size_t)(i >> 8) * W + (i & 255), Sf[i]);
}

// ---------------------------------------------------------------------------
extern "C" void kernel_launch(void* const* d_in, const int* in_sizes, int n_in,
                              void* d_out, int out_size) {
    (void)in_sizes; (void)n_in; (void)out_size;
    const float* x = (const float*)d_in[0];   // (B,C,H,W)
    const float* w = (const float*)d_in[1];   // (O,C,H,W)
    float* out = (float*)d_out;               // (B,O,H,W)

    __half2 *xr, *wr, *xf, *wf, *yf, *yr;
    cudaGetSymbolAddress((void**)&xr, g_xr);
    cudaGetSymbolAddress((void**)&wr, g_wr);
    cudaGetSymbolAddress((void**)&xf, g_xf);
    cudaGetSymbolAddress((void**)&wf, g_wf);
    cudaGetSymbolAddress((void**)&yf, g_yf);
    cudaGetSymbolAddress((void**)&yr, g_yr);

    // W path first, then X path: every 67MB intermediate (xr, xf, yf, yr) is
    // consumed by the kernel immediately after its producer -> L2 resident.
    k_rowfft<<<NIMG_W * 8, 256>>>(w, wr, NIMG_W);
    k_colfft<<<dim3(KW, NIMG_W / 16), 256>>>(wr, wf, NIMG_W);
    k_rowfft<<<NIMG_X * 8, 256>>>(x, xr, NIMG_X);
    k_colfft<<<dim3(KW, NIMG_X / 16), 256>>>(xr, xf, NIMG_X);
    // Per-bin channel contraction on tensor cores (4 bins/block, 1 warp/bin)
    k_bingemm<<<(H * KW) / 4, 128>>>(xf, wf, yf);
    // Inverse column FFT (fp16 in/out)
    k_icolfft<<<dim3(KW, NIMG_Y / 16), 256>>>(yf, yr, NIMG_Y);
    // Packed inverse row FFT -> real output
    k_irowfft<<<NIMG_Y * 8, 256>>>(yr, out, NIMG_Y);
}

// round 9
// speedup vs baseline: 3.0380x; 1.0090x over previous
#include <cuda_runtime.h>
#include <cuda_fp16.h>
#include <cstddef>

// Problem constants
#define H 256
#define W 256
#define KW 129          // rfft bins along W
#define B_ 16
#define C_ 32
#define O_ 32
#define NIMG_X (B_*C_)  // 512
#define NIMG_W (O_*C_)  // 1024
#define NIMG_Y (B_*O_)  // 512

// ---------------- scratch (static device globals; allocation-free) ----------
__device__ __half2 g_xr[(size_t)KW * NIMG_X * H];
__device__ __half2 g_wr[(size_t)KW * NIMG_W * H];
__device__ __half2 g_xf[(size_t)H * KW * NIMG_X];
__device__ __half2 g_wf[(size_t)H * KW * NIMG_W];
__device__ __half2 g_yf[(size_t)H * KW * NIMG_Y];
__device__ __half2 g_yr[(size_t)KW * NIMG_Y * H];
__device__ float2  g_twd[256];   // W_256^i forward twiddles

__device__ __forceinline__ float2 cmulf(float2 a, float2 b) {
    return make_float2(fmaf(a.x, b.x, -a.y * b.y), fmaf(a.x, b.y, a.y * b.x));
}
__device__ __forceinline__ __half2 f2h(float2 v) { return __floats2half2_rn(v.x, v.y); }
__device__ __forceinline__ float2 h2f(__half2 v) { return __half22float2(v); }
// streaming (last-use) half2 load
__device__ __forceinline__ __half2 ldcs_h2(const __half2* p) {
    unsigned u = __ldcs((const unsigned*)p);
    return *reinterpret_cast<__half2*>(&u);
}

// ---------------- K0: build twiddle table once per call ---------------------
__global__ void k_twd() {
    const int i = threadIdx.x;
    float sn, cs;
    sincosf(-6.283185307179586f * (float)i / 256.0f, &sn, &cs);
    g_twd[i] = make_float2(cs, sn);
}

// ---------------- in-register FFT-16 (Stockham radix-2, 4 stages) -----------
template <bool INV>
__device__ __forceinline__ void fft16r(float2* a) {
    const float TR[8] = { 1.f,  0.9238795325112867f,  0.7071067811865476f,  0.3826834323650898f,
                          0.f, -0.3826834323650898f, -0.7071067811865476f, -0.9238795325112867f };
    const float TI[8] = { 0.f, -0.3826834323650898f, -0.7071067811865476f, -0.9238795325112867f,
                         -1.f, -0.9238795325112867f, -0.7071067811865476f, -0.9238795325112867f };
    // NOTE: last constant corrected below; see TI_fix
    float2 b[16];
    float2 *s = a, *d = b;
    const float TI7 = -0.3826834323650898f;
#pragma unroll
    for (int st = 0; st < 4; st++) {
        const int S = 1 << st;
#pragma unroll
        for (int t = 0; t < 8; t++) {
            const int j = t & ~(S - 1);
            const float wr = TR[j];
            float ti = (j == 7) ? TI7 : TI[j];
            const float wi = INV ? -ti : ti;
            float2 u = s[t], v = s[t + 8];
            float2 sum = make_float2(u.x + v.x, u.y + v.y);
            float2 dif = make_float2(u.x - v.x, u.y - v.y);
            d[t + j]     = sum;
            d[t + j + S] = make_float2(fmaf(dif.x, wr, -dif.y * wi),
                                       fmaf(dif.x, wi,  dif.y * wr));
        }
        float2* tmp = s; s = d; d = tmp;
    }
}

// ---------------- FFT-256 on registers: 16 threads x 16 points --------------
template <bool INV>
__device__ __forceinline__ void fft256_regs(float2* a, float2* S,
                                            const float2* twd, int row, int t) {
    fft16r<INV>(a);
#pragma unroll
    for (int k2 = 0; k2 < 16; k2++) {
        float2 w = twd[t * k2];
        if (INV) w.y = -w.y;
        a[k2] = cmulf(a[k2], w);
    }
    float2* Sr = S + row * 272;
    __syncwarp();
#pragma unroll
    for (int k2 = 0; k2 < 16; k2++) Sr[t * 17 + k2] = a[k2];
    __syncwarp();
#pragma unroll
    for (int n1 = 0; n1 < 16; n1++) a[n1] = Sr[n1 * 17 + t];
    __syncwarp();
    fft16r<INV>(a);
}

// ---------------- K1: packed row FFT (2 real rows per complex FFT) ----------
__global__ void __launch_bounds__(256) k_rowfft(const float* __restrict__ in,
                                                __half2* __restrict__ out, int nimg) {
    __shared__ float2 S[4352];
    __shared__ float2 twd[256];
    const int tid = threadIdx.x, row = tid >> 4, t = tid & 15;
    const int img = blockIdx.x >> 3, h0 = (blockIdx.x & 7) << 5;
    twd[tid] = g_twd[tid];
    const float* pa = in + ((size_t)img * H + h0 + 2 * row) * W + t;
    const float* pb = pa + W;
    float2 a[16];
#pragma unroll
    for (int q = 0; q < 16; q++) a[q] = make_float2(__ldcs(pa + q * 16), __ldcs(pb + q * 16));
    __syncthreads();
    fft256_regs<false>(a, S, twd, row, t);
    __syncthreads();
#pragma unroll
    for (int k1 = 0; k1 < 16; k1++) S[(k1 * 16 + t) * 17 + row] = a[k1];
    __syncthreads();
    const size_t ob = (size_t)img * H + h0;
    for (int i = tid; i < KW * 32; i += 256) {
        const int kw_ = i >> 5, hh = i & 31, r = hh >> 1;
        const float2 Z  = S[kw_ * 17 + r];
        const float2 Zc = S[((256 - kw_) & 255) * 17 + r];
        float2 v;
        if ((hh & 1) == 0)
            v = make_float2((Z.x + Zc.x) * 0.5f, (Z.y - Zc.y) * 0.5f);
        else
            v = make_float2((Z.y + Zc.y) * 0.5f, (Zc.x - Z.x) * 0.5f);
        out[(size_t)kw_ * nimg * H + ob + hh] = f2h(v);
    }
}

// ---------------- K2: column FFT -> bin-major [kh][KW][nimg] (fp16) ---------
__global__ void __launch_bounds__(256) k_colfft(const __half2* __restrict__ in,
                                                __half2* __restrict__ out, int nimg) {
    __shared__ float2 S[4352];
    __shared__ float2 twd[256];
    const int tid = threadIdx.x, row = tid >> 4, t = tid & 15;
    const int kw = blockIdx.x, img0 = blockIdx.y << 4;
    twd[tid] = g_twd[tid];
    const __half2* src = in + ((size_t)kw * nimg + img0 + row) * H + t;
    float2 a[16];
#pragma unroll
    for (int q = 0; q < 16; q++) a[q] = h2f(ldcs_h2(src + q * 16));
    __syncthreads();
    fft256_regs<false>(a, S, twd, row, t);
    __syncthreads();
#pragma unroll
    for (int k1 = 0; k1 < 16; k1++) S[(k1 * 16 + t) * 17 + row] = a[k1];
    __syncthreads();
    for (int i = tid; i < 4096; i += 256) {
        const int kh = i >> 4, im = i & 15;
        out[((size_t)kh * KW + kw) * nimg + img0 + im] = f2h(S[kh * 17 + im]);
    }
}

// ---------------- K3: per-bin contraction on tensor cores (mma.sync) --------
__device__ __forceinline__ void mma16816(float* c, const unsigned* a, unsigned b0, unsigned b1) {
    asm volatile("mma.sync.aligned.m16n8k16.row.col.f32.f16.f16.f32 "
                 "{%0,%1,%2,%3}, {%4,%5,%6,%7}, {%8,%9}, {%0,%1,%2,%3};"
                 : "+f"(c[0]), "+f"(c[1]), "+f"(c[2]), "+f"(c[3])
                 : "r"(a[0]), "r"(a[1]), "r"(a[2]), "r"(a[3]), "r"(b0), "r"(b1));
}

__global__ void __launch_bounds__(128) k_bingemm(const __half2* __restrict__ xf,
                                                 const __half2* __restrict__ wf,
                                                 __half2* __restrict__ yf) {
    __shared__ unsigned xs[4][16 * 36];   // [bin][b*36 + cpair], padded stride 36
    __shared__ unsigned ws[4][32 * 36];   // [bin][o*36 + cpair]
    const int tid = threadIdx.x;
    const size_t gbin0 = (size_t)blockIdx.x * 4;
    const unsigned* xg = (const unsigned*)(xf + gbin0 * NIMG_X);
    const unsigned* wg = (const unsigned*)(wf + gbin0 * NIMG_W);
    for (int i = tid; i < 4 * 512; i += 128) {
        const int lb = i >> 9, j = i & 511;
        xs[lb][(j >> 5) * 36 + (j & 31)] = __ldcs(xg + lb * 512 + j);
    }
    for (int i = tid; i < 4 * 1024; i += 128) {
        const int lb = i >> 10, j = i & 1023;
        ws[lb][(j >> 5) * 36 + (j & 31)] = __ldcs(wg + lb * 1024 + j);
    }
    __syncthreads();
    const int wp = tid >> 5, lane = tid & 31, r = lane >> 2, q = lane & 3;
    const unsigned* X = xs[wp];
    const unsigned* Wm = ws[wp];
    float cre[4][4] = {{0}}, cim[4][4] = {{0}};
#pragma unroll
    for (int kc = 0; kc < 4; kc++) {
        unsigned a[4];
        a[0] = X[r * 36 + kc * 8 + q];
        a[1] = X[(r + 8) * 36 + kc * 8 + q];
        a[2] = X[r * 36 + kc * 8 + 4 + q];
        a[3] = X[(r + 8) * 36 + kc * 8 + 4 + q];
#pragma unroll
        for (int ot = 0; ot < 4; ot++) {
            const unsigned w0 = Wm[(ot * 8 + r) * 36 + kc * 8 + q];
            const unsigned w1 = Wm[(ot * 8 + r) * 36 + kc * 8 + 4 + q];
            mma16816(cre[ot], a, w0 ^ 0x80000000u, w1 ^ 0x80000000u);   // (wr,-wi)
            mma16816(cim[ot], a, __byte_perm(w0, w0, 0x1032),           // (wi,wr)
                                  __byte_perm(w1, w1, 0x1032));
        }
    }
    __half2* Y = yf + (gbin0 + wp) * NIMG_Y;
#pragma unroll
    for (int ot = 0; ot < 4; ot++) {
        const int o0 = ot * 8 + 2 * q;
        Y[r * 32 + o0]           = f2h(make_float2(cre[ot][0], cim[ot][0]));
        Y[r * 32 + o0 + 1]       = f2h(make_float2(cre[ot][1], cim[ot][1]));
        Y[(r + 8) * 32 + o0]     = f2h(make_float2(cre[ot][2], cim[ot][2]));
        Y[(r + 8) * 32 + o0 + 1] = f2h(make_float2(cre[ot][3], cim[ot][3]));
    }
}

// ---------------- K4: inverse column FFT -> [kw][nimg][h], scale 1/256 ------
__global__ void __launch_bounds__(256) k_icolfft(const __half2* __restrict__ in,
                                                 __half2* __restrict__ out, int nimg) {
    __shared__ float2 S[4352];
    __shared__ float2 twd[256];
    const int tid = threadIdx.x, row = tid >> 4, t = tid & 15;
    const int kw = blockIdx.x, img0 = blockIdx.y << 4;
    twd[tid] = g_twd[tid];
    for (int i = tid; i < 4096; i += 256) {
        const int kh = i >> 4, im = i & 15;
        S[kh * 17 + im] = h2f(ldcs_h2(in + ((size_t)kh * KW + kw) * nimg + img0 + im));
    }
    __syncthreads();
    float2 a[16];
#pragma unroll
    for (int q = 0; q < 16; q++) a[q] = S[(q * 16 + t) * 17 + row];
    __syncthreads();
    fft256_regs<true>(a, S, twd, row, t);
    __syncthreads();
    const float sc = 1.0f / 256.0f;
#pragma unroll
    for (int k1 = 0; k1 < 16; k1++)
        S[row * 256 + k1 * 16 + t] = make_float2(a[k1].x * sc, a[k1].y * sc);
    __syncthreads();
    for (int i = tid; i < 4096; i += 256) {
        const int im = i >> 8, h = i & 255;
        out[((size_t)kw * nimg + img0 + im) * H + h] = f2h(S[im * 256 + h]);
    }
}

// ---------------- K5: packed inverse row FFT (2 real rows per iFFT) ---------
__global__ void __launch_bounds__(256) k_irowfft(const __half2* __restrict__ in,
                                                 float* __restrict__ out, int nimg) {
    __shared__ float2 S[4352];
    __shared__ float2 twd[256];
    const int tid = threadIdx.x, row = tid >> 4, t = tid & 15;
    const int img = blockIdx.x >> 3, h0 = (blockIdx.x & 7) << 5;
    twd[tid] = g_twd[tid];
    for (int i = tid; i < KW * 32; i += 256) {
        const int kw_ = i >> 5, hh = i & 31;
        S[kw_ * 33 + hh] = h2f(ldcs_h2(in + (size_t)kw_ * nimg * H + (size_t)img * H + h0 + hh));
    }
    __syncthreads();
    float2 a[16];
#pragma unroll
    for (int q = 0; q < 16; q++) {
        const int n = q * 16 + t;
        if (n <= 128) {
            const float2 ya = S[n * 33 + 2 * row];
            const float2 yb = S[n * 33 + 2 * row + 1];
            a[q] = make_float2(ya.x - yb.y, ya.y + yb.x);        // Ya + i*Yb
        } else {
            const int m = 256 - n;
            const float2 ya = S[m * 33 + 2 * row];
            const float2 yb = S[m * 33 + 2 * row + 1];
            a[q] = make_float2(ya.x + yb.y, yb.x - ya.y);        // conj(Ya)+i*conj(Yb)
        }
    }
    __syncthreads();
    fft256_regs<true>(a, S, twd, row, t);
    __syncthreads();
    float* Sf = (float*)S;
    const float sc = 1.0f / 256.0f;
#pragma unroll
    for (int k1 = 0; k1 < 16; k1++) {
        const int idx = k1 * 16 + t;
        Sf[(2 * row) * 256 + idx]     = a[k1].x * sc;
        Sf[(2 * row + 1) * 256 + idx] = a[k1].y * sc;
    }
    __syncthreads();
    const size_t ob = ((size_t)img * H + h0) * W;
    for (int i = tid; i < 8192; i += 256)
        __stcs(out + ob + (size_t)(i >> 8) * W + (i & 255), Sf[i]);
}

// ---------------------------------------------------------------------------
extern "C" void kernel_launch(void* const* d_in, const int* in_sizes, int n_in,
                              void* d_out, int out_size) {
    (void)in_sizes; (void)n_in; (void)out_size;
    const float* x = (const float*)d_in[0];   // (B,C,H,W)
    const float* w = (const float*)d_in[1];   // (O,C,H,W)
    float* out = (float*)d_out;               // (B,O,H,W)

    __half2 *xr, *wr, *xf, *wf, *yf, *yr;
    cudaGetSymbolAddress((void**)&xr, g_xr);
    cudaGetSymbolAddress((void**)&wr, g_wr);
    cudaGetSymbolAddress((void**)&xf, g_xf);
    cudaGetSymbolAddress((void**)&wf, g_wf);
    cudaGetSymbolAddress((void**)&yf, g_yf);
    cudaGetSymbolAddress((void**)&yr, g_yr);

    // Twiddle table (replaces per-block sincosf in every FFT kernel)
    k_twd<<<1, 256>>>();
    // W path first, then X path: every 67MB intermediate (xr, xf, yf, yr) is
    // consumed by the kernel immediately after its producer -> L2 resident.
    k_rowfft<<<NIMG_W * 8, 256>>>(w, wr, NIMG_W);
    k_colfft<<<dim3(KW, NIMG_W / 16), 256>>>(wr, wf, NIMG_W);
    k_rowfft<<<NIMG_X * 8, 256>>>(x, xr, NIMG_X);
    k_colfft<<<dim3(KW, NIMG_X / 16), 256>>>(xr, xf, NIMG_X);
    // Per-bin channel contraction on tensor cores (4 bins/block, 1 warp/bin)
    k_bingemm<<<(H * KW) / 4, 128>>>(xf, wf, yf);
    // Inverse column FFT (fp16 in/out)
    k_icolfft<<<dim3(KW, NIMG_Y / 16), 256>>>(yf, yr, NIMG_Y);
    // Packed inverse row FFT -> real output
    k_irowfft<<<NIMG_Y * 8, 256>>>(yr, out, NIMG_Y);
}

// round 10
// speedup vs baseline: 3.0519x; 1.0046x over previous
#include <cuda_runtime.h>
#include <cuda_fp16.h>
#include <cstddef>

// Problem constants
#define H 256
#define W 256
#define KW 129          // rfft bins along W
#define B_ 16
#define C_ 32
#define O_ 32
#define NIMG_X (B_*C_)  // 512
#define NIMG_W (O_*C_)  // 1024
#define NIMG_Y (B_*O_)  // 512

// ---------------- scratch (static device globals; allocation-free) ----------
__device__ __half2 g_xr[(size_t)KW * NIMG_X * H];
__device__ __half2 g_wr[(size_t)KW * NIMG_W * H];
__device__ __half2 g_xf[(size_t)H * KW * NIMG_X];
__device__ __half2 g_wf[(size_t)H * KW * NIMG_W];
__device__ __half2 g_yf[(size_t)H * KW * NIMG_Y];
__device__ __half2 g_yr[(size_t)KW * NIMG_Y * H];
__device__ float2  g_twd[256];   // W_256^i forward twiddles

__device__ __forceinline__ float2 cmulf(float2 a, float2 b) {
    return make_float2(fmaf(a.x, b.x, -a.y * b.y), fmaf(a.x, b.y, a.y * b.x));
}
__device__ __forceinline__ __half2 f2h(float2 v) { return __floats2half2_rn(v.x, v.y); }
__device__ __forceinline__ float2 h2f(__half2 v) { return __half22float2(v); }
// streaming (last-use) half2 load
__device__ __forceinline__ __half2 ldcs_h2(const __half2* p) {
    unsigned u = __ldcs((const unsigned*)p);
    return *reinterpret_cast<__half2*>(&u);
}

// ---------------- K0: build twiddle table once per call ---------------------
__global__ void k_twd() {
    const int i = threadIdx.x;
    float sn, cs;
    sincosf(-6.283185307179586f * (float)i / 256.0f, &sn, &cs);
    g_twd[i] = make_float2(cs, sn);
}

// ---------------- in-register FFT-16 (Stockham radix-2, 4 stages) -----------
template <bool INV>
__device__ __forceinline__ void fft16r(float2* a) {
    const float TR[8] = { 1.f,  0.9238795325112867f,  0.7071067811865476f,  0.3826834323650898f,
                          0.f, -0.3826834323650898f, -0.7071067811865476f, -0.9238795325112867f };
    const float TI[8] = { 0.f, -0.3826834323650898f, -0.7071067811865476f, -0.9238795325112867f,
                         -1.f, -0.9238795325112867f, -0.7071067811865476f, -0.3826834323650898f };
    float2 b[16];
    float2 *s = a, *d = b;
#pragma unroll
    for (int st = 0; st < 4; st++) {
        const int S = 1 << st;
#pragma unroll
        for (int t = 0; t < 8; t++) {
            const int j = t & ~(S - 1);
            const float wr = TR[j];
            const float wi = INV ? -TI[j] : TI[j];
            float2 u = s[t], v = s[t + 8];
            float2 sum = make_float2(u.x + v.x, u.y + v.y);
            float2 dif = make_float2(u.x - v.x, u.y - v.y);
            d[t + j]     = sum;
            d[t + j + S] = make_float2(fmaf(dif.x, wr, -dif.y * wi),
                                       fmaf(dif.x, wi,  dif.y * wr));
        }
        float2* tmp = s; s = d; d = tmp;
    }
}

// ---------------- FFT-256 on registers: 16 threads x 16 points --------------
template <bool INV>
__device__ __forceinline__ void fft256_regs(float2* a, float2* S,
                                            const float2* twd, int row, int t) {
    fft16r<INV>(a);
#pragma unroll
    for (int k2 = 0; k2 < 16; k2++) {
        float2 w = twd[t * k2];
        if (INV) w.y = -w.y;
        a[k2] = cmulf(a[k2], w);
    }
    float2* Sr = S + row * 272;
    __syncwarp();
#pragma unroll
    for (int k2 = 0; k2 < 16; k2++) Sr[t * 17 + k2] = a[k2];
    __syncwarp();
#pragma unroll
    for (int n1 = 0; n1 < 16; n1++) a[n1] = Sr[n1 * 17 + t];
    __syncwarp();
    fft16r<INV>(a);
}

// ---------------- K1: packed row FFT (2 real rows per complex FFT) ----------
__global__ void __launch_bounds__(256) k_rowfft(const float* __restrict__ in,
                                                __half2* __restrict__ out, int nimg) {
    __shared__ float2 S[4352];
    __shared__ float2 twd[256];
    const int tid = threadIdx.x, row = tid >> 4, t = tid & 15;
    const int img = blockIdx.x >> 3, h0 = (blockIdx.x & 7) << 5;
    twd[tid] = g_twd[tid];
    const float* pa = in + ((size_t)img * H + h0 + 2 * row) * W + t;
    const float* pb = pa + W;
    float2 a[16];
#pragma unroll
    for (int q = 0; q < 16; q++) a[q] = make_float2(__ldcs(pa + q * 16), __ldcs(pb + q * 16));
    __syncthreads();
    fft256_regs<false>(a, S, twd, row, t);
    __syncthreads();
#pragma unroll
    for (int k1 = 0; k1 < 16; k1++) S[(k1 * 16 + t) * 17 + row] = a[k1];
    __syncthreads();
    const size_t ob = (size_t)img * H + h0;
    for (int i = tid; i < KW * 32; i += 256) {
        const int kw_ = i >> 5, hh = i & 31, r = hh >> 1;
        const float2 Z  = S[kw_ * 17 + r];
        const float2 Zc = S[((256 - kw_) & 255) * 17 + r];
        float2 v;
        if ((hh & 1) == 0)
            v = make_float2((Z.x + Zc.x) * 0.5f, (Z.y - Zc.y) * 0.5f);
        else
            v = make_float2((Z.y + Zc.y) * 0.5f, (Zc.x - Z.x) * 0.5f);
        out[(size_t)kw_ * nimg * H + ob + hh] = f2h(v);
    }
}

// ---------------- K2: column FFT -> bin-major [kh][KW][nimg] (fp16) ---------
__global__ void __launch_bounds__(256) k_colfft(const __half2* __restrict__ in,
                                                __half2* __restrict__ out, int nimg) {
    __shared__ float2 S[4352];
    __shared__ float2 twd[256];
    const int tid = threadIdx.x, row = tid >> 4, t = tid & 15;
    const int kw = blockIdx.x, img0 = blockIdx.y << 4;
    twd[tid] = g_twd[tid];
    const __half2* src = in + ((size_t)kw * nimg + img0 + row) * H + t;
    float2 a[16];
#pragma unroll
    for (int q = 0; q < 16; q++) a[q] = h2f(ldcs_h2(src + q * 16));
    __syncthreads();
    fft256_regs<false>(a, S, twd, row, t);
    __syncthreads();
#pragma unroll
    for (int k1 = 0; k1 < 16; k1++) S[(k1 * 16 + t) * 17 + row] = a[k1];
    __syncthreads();
    for (int i = tid; i < 4096; i += 256) {
        const int kh = i >> 4, im = i & 15;
        out[((size_t)kh * KW + kw) * nimg + img0 + im] = f2h(S[kh * 17 + im]);
    }
}

// ---------------- K3: per-bin contraction on tensor cores (mma.sync) --------
__device__ __forceinline__ void mma16816(float* c, const unsigned* a, unsigned b0, unsigned b1) {
    asm volatile("mma.sync.aligned.m16n8k16.row.col.f32.f16.f16.f32 "
                 "{%0,%1,%2,%3}, {%4,%5,%6,%7}, {%8,%9}, {%0,%1,%2,%3};"
                 : "+f"(c[0]), "+f"(c[1]), "+f"(c[2]), "+f"(c[3])
                 : "r"(a[0]), "r"(a[1]), "r"(a[2]), "r"(a[3]), "r"(b0), "r"(b1));
}

__global__ void __launch_bounds__(128) k_bingemm(const __half2* __restrict__ xf,
                                                 const __half2* __restrict__ wf,
                                                 __half2* __restrict__ yf) {
    __shared__ unsigned xs[4][16 * 36];   // [bin][b*36 + cpair]; reused for C staging
    __shared__ unsigned ws[4][32 * 36];   // [bin][o*36 + cpair]
    const int tid = threadIdx.x;
    const size_t gbin0 = (size_t)blockIdx.x * 4;
    const unsigned* xg = (const unsigned*)(xf + gbin0 * NIMG_X);
    const unsigned* wg = (const unsigned*)(wf + gbin0 * NIMG_W);
    for (int i = tid; i < 4 * 512; i += 128) {
        const int lb = i >> 9, j = i & 511;
        xs[lb][(j >> 5) * 36 + (j & 31)] = __ldcs(xg + lb * 512 + j);
    }
    for (int i = tid; i < 4 * 1024; i += 128) {
        const int lb = i >> 10, j = i & 1023;
        ws[lb][(j >> 5) * 36 + (j & 31)] = __ldcs(wg + lb * 1024 + j);
    }
    __syncthreads();
    const int wp = tid >> 5, lane = tid & 31, r = lane >> 2, q = lane & 3;
    unsigned* X = xs[wp];                 // warp-private region
    const unsigned* Wm = ws[wp];
    float cre[4][4] = {{0}}, cim[4][4] = {{0}};
#pragma unroll
    for (int kc = 0; kc < 4; kc++) {
        unsigned a[4];
        a[0] = X[r * 36 + kc * 8 + q];
        a[1] = X[(r + 8) * 36 + kc * 8 + q];
        a[2] = X[r * 36 + kc * 8 + 4 + q];
        a[3] = X[(r + 8) * 36 + kc * 8 + 4 + q];
#pragma unroll
        for (int ot = 0; ot < 4; ot++) {
            const unsigned w0 = Wm[(ot * 8 + r) * 36 + kc * 8 + q];
            const unsigned w1 = Wm[(ot * 8 + r) * 36 + kc * 8 + 4 + q];
            mma16816(cre[ot], a, w0 ^ 0x80000000u, w1 ^ 0x80000000u);   // (wr,-wi)
            mma16816(cim[ot], a, __byte_perm(w0, w0, 0x1032),           // (wi,wr)
                                  __byte_perm(w1, w1, 0x1032));
        }
    }
    // Stage C fragments into xs[wp] (own region, dead after the MMA loop),
    // padded stride 33, then block-wide coalesced copy-out to gmem.
#pragma unroll
    for (int ot = 0; ot < 4; ot++) {
        const int o0 = ot * 8 + 2 * q;
        __half2 v;
        v = f2h(make_float2(cre[ot][0], cim[ot][0])); X[r * 33 + o0]           = reinterpret_cast<unsigned&>(v);
        v = f2h(make_float2(cre[ot][1], cim[ot][1])); X[r * 33 + o0 + 1]       = reinterpret_cast<unsigned&>(v);
        v = f2h(make_float2(cre[ot][2], cim[ot][2])); X[(r + 8) * 33 + o0]     = reinterpret_cast<unsigned&>(v);
        v = f2h(make_float2(cre[ot][3], cim[ot][3])); X[(r + 8) * 33 + o0 + 1] = reinterpret_cast<unsigned&>(v);
    }
    __syncthreads();
    unsigned* yg = (unsigned*)(yf + gbin0 * NIMG_Y);
    for (int i = tid; i < 4 * 512; i += 128) {
        const int lb = i >> 9, j = i & 511;
        yg[lb * 512 + j] = xs[lb][(j >> 5) * 33 + (j & 31)];
    }
}

// ---------------- K4: inverse column FFT -> [kw][nimg][h], scale 1/256 ------
__global__ void __launch_bounds__(256) k_icolfft(const __half2* __restrict__ in,
                                                 __half2* __restrict__ out, int nimg) {
    __shared__ float2 S[4352];
    __shared__ float2 twd[256];
    const int tid = threadIdx.x, row = tid >> 4, t = tid & 15;
    const int kw = blockIdx.x, img0 = blockIdx.y << 4;
    twd[tid] = g_twd[tid];
    for (int i = tid; i < 4096; i += 256) {
        const int kh = i >> 4, im = i & 15;
        S[kh * 17 + im] = h2f(ldcs_h2(in + ((size_t)kh * KW + kw) * nimg + img0 + im));
    }
    __syncthreads();
    float2 a[16];
#pragma unroll
    for (int q = 0; q < 16; q++) a[q] = S[(q * 16 + t) * 17 + row];
    __syncthreads();
    fft256_regs<true>(a, S, twd, row, t);
    __syncthreads();
    const float sc = 1.0f / 256.0f;
#pragma unroll
    for (int k1 = 0; k1 < 16; k1++)
        S[row * 256 + k1 * 16 + t] = make_float2(a[k1].x * sc, a[k1].y * sc);
    __syncthreads();
    for (int i = tid; i < 4096; i += 256) {
        const int im = i >> 8, h = i & 255;
        out[((size_t)kw * nimg + img0 + im) * H + h] = f2h(S[im * 256 + h]);
    }
}

// ---------------- K5: packed inverse row FFT (2 real rows per iFFT) ---------
__global__ void __launch_bounds__(256) k_irowfft(const __half2* __restrict__ in,
                                                 float* __restrict__ out, int nimg) {
    __shared__ float2 S[4352];
    __shared__ float2 twd[256];
    const int tid = threadIdx.x, row = tid >> 4, t = tid & 15;
    const int img = blockIdx.x >> 3, h0 = (blockIdx.x & 7) << 5;
    twd[tid] = g_twd[tid];
    for (int i = tid; i < KW * 32; i += 256) {
        const int kw_ = i >> 5, hh = i & 31;
        S[kw_ * 33 + hh] = h2f(ldcs_h2(in + (size_t)kw_ * nimg * H + (size_t)img * H + h0 + hh));
    }
    __syncthreads();
    float2 a[16];
#pragma unroll
    for (int q = 0; q < 16; q++) {
        const int n = q * 16 + t;
        if (n <= 128) {
            const float2 ya = S[n * 33 + 2 * row];
            const float2 yb = S[n * 33 + 2 * row + 1];
            a[q] = make_float2(ya.x - yb.y, ya.y + yb.x);        // Ya + i*Yb
        } else {
            const int m = 256 - n;
            const float2 ya = S[m * 33 + 2 * row];
            const float2 yb = S[m * 33 + 2 * row + 1];
            a[q] = make_float2(ya.x + yb.y, yb.x - ya.y);        // conj(Ya)+i*conj(Yb)
        }
    }
    __syncthreads();
    fft256_regs<true>(a, S, twd, row, t);
    __syncthreads();
    float* Sf = (float*)S;
    const float sc = 1.0f / 256.0f;
#pragma unroll
    for (int k1 = 0; k1 < 16; k1++) {
        const int idx = k1 * 16 + t;
        Sf[(2 * row) * 256 + idx]     = a[k1].x * sc;
        Sf[(2 * row + 1) * 256 + idx] = a[k1].y * sc;
    }
    __syncthreads();
    const size_t ob = ((size_t)img * H + h0) * W;
    for (int i = tid; i < 8192; i += 256)
        __stcs(out + ob + (size_t)(i >> 8) * W + (i & 255), Sf[i]);
}

// ---------------------------------------------------------------------------
extern "C" void kernel_launch(void* const* d_in, const int* in_sizes, int n_in,
                              void* d_out, int out_size) {
    (void)in_sizes; (void)n_in; (void)out_size;
    const float* x = (const float*)d_in[0];   // (B,C,H,W)
    const float* w = (const float*)d_in[1];   // (O,C,H,W)
    float* out = (float*)d_out;               // (B,O,H,W)

    __half2 *xr, *wr, *xf, *wf, *yf, *yr;
    cudaGetSymbolAddress((void**)&xr, g_xr);
    cudaGetSymbolAddress((void**)&wr, g_wr);
    cudaGetSymbolAddress((void**)&xf, g_xf);
    cudaGetSymbolAddress((void**)&wf, g_wf);
    cudaGetSymbolAddress((void**)&yf, g_yf);
    cudaGetSymbolAddress((void**)&yr, g_yr);

    // Twiddle table (replaces per-block sincosf in every FFT kernel)
    k_twd<<<1, 256>>>();
    // W path first, then X path: every 67MB intermediate (xr, xf, yf, yr) is
    // consumed by the kernel immediately after its producer -> L2 resident.
    k_rowfft<<<NIMG_W * 8, 256>>>(w, wr, NIMG_W);
    k_colfft<<<dim3(KW, NIMG_W / 16), 256>>>(wr, wf, NIMG_W);
    k_rowfft<<<NIMG_X * 8, 256>>>(x, xr, NIMG_X);
    k_colfft<<<dim3(KW, NIMG_X / 16), 256>>>(xr, xf, NIMG_X);
    // Per-bin channel contraction on tensor cores (4 bins/block, 1 warp/bin)
    k_bingemm<<<(H * KW) / 4, 128>>>(xf, wf, yf);
    // Inverse column FFT (fp16 in/out)
    k_icolfft<<<dim3(KW, NIMG_Y / 16), 256>>>(yf, yr, NIMG_Y);
    // Packed inverse row FFT -> real output
    k_irowfft<<<NIMG_Y * 8, 256>>>(yr, out, NIMG_Y);
}